// round 2
// baseline (speedup 1.0000x reference)
#include <cuda_runtime.h>
#include <math.h>

#define HW   4096
#define NB   8
#define NFC  768
#define NRC  8
#define NP   8

typedef unsigned long long ull;

// ---------------- scratch (device globals; no allocation allowed) ----------------
__device__ float g_cpre[NB*NRC*HW];   // gelu(conv1x1(feature_map))
__device__ float g_car [NB*NRC*HW];   // carrier = gelu(conv3x3(g_cpre))
__device__ float g_cm  [NB*HW];       // carrier channel mean
__device__ float g_dn  [NB*HW];       // mean |carrier|  (density_raw)
__device__ float g_hp  [NB*HW];       // carrier_hp
__device__ float g_cs  [NB*HW];       // avg3(|hp|)
__device__ float g_g0  [NB*HW];       // sigmoid((ev-THR)/TEMP)
__device__ float g_er  [NB*HW];       // eroded mask (minp5 of m0)
__device__ float g_s0  [NB*HW];       // ss before avg3-subtract
__device__ float g_sf  [NB*HW];       // final ss
__device__ float g_st  [NB*8];        // per-image stats: csmn,csmx,dmn,dmx,dmean

// ---------------- helpers ----------------
__device__ __forceinline__ ull pack2(float lo, float hi){ ull r; asm("mov.b64 %0,{%1,%2};":"=l"(r):"f"(lo),"f"(hi)); return r; }
__device__ __forceinline__ ull fma2(ull a, ull b, ull c){ ull d; asm("fma.rn.f32x2 %0,%1,%2,%3;":"=l"(d):"l"(a),"l"(b),"l"(c)); return d; }
__device__ __forceinline__ void unpack2(ull v, float&lo, float&hi){ asm("mov.b64 {%0,%1},%2;":"=f"(lo),"=f"(hi):"l"(v)); }
__device__ __forceinline__ float geluf(float x){ return 0.5f*x*(1.0f+erff(x*0.70710678118654752f)); }
__device__ __forceinline__ float sigm(float x){ return 1.0f/(1.0f+expf(-x)); }

// ---------------- K1: 768 -> 8 1x1 conv + gelu (reads 100MB) ----------------
__global__ __launch_bounds__(128) void k1_gemm(const float* __restrict__ fm,
                                               const float* __restrict__ w,
                                               const float* __restrict__ bv){
    __shared__ ull ws[NFC*NRC];                       // (w,w) packed, c-major
    for (int i = threadIdx.x; i < NFC*NRC; i += 128){
        int c = i >> 3, r = i & 7;
        float v = w[r*NFC + c];
        ws[i] = pack2(v, v);
    }
    __syncthreads();
    int t = blockIdx.x*128 + threadIdx.x;             // 0..16383
    int b = t >> 11; int p = (t & 2047) << 1;         // pixel pair
    const float* x = fm + (size_t)b*NFC*HW + p;
    ull acc[NRC];
    #pragma unroll
    for (int r = 0; r < NRC; r++){ float bb = bv[r]; acc[r] = pack2(bb, bb); }
    #pragma unroll 8
    for (int c = 0; c < NFC; c++){
        ull xv = *(const ull*)(x + (size_t)c*HW);
        const ull* wc = ws + c*8;
        #pragma unroll
        for (int r = 0; r < NRC; r++) acc[r] = fma2(wc[r], xv, acc[r]);
    }
    float* o = g_cpre + (size_t)b*NRC*HW + p;
    #pragma unroll
    for (int r = 0; r < NRC; r++){
        float lo, hi; unpack2(acc[r], lo, hi);
        float2 v; v.x = geluf(lo); v.y = geluf(hi);
        *(float2*)(o + (size_t)r*HW) = v;
    }
}

// ---------------- K2: 3x3 conv 8->8 + gelu + channel stats ----------------
__global__ __launch_bounds__(256) void k2_conv3(const float* __restrict__ w,
                                                const float* __restrict__ bv){
    __shared__ float ws[NRC*NRC*9];
    __shared__ float bs[NRC];
    for (int i = threadIdx.x; i < NRC*NRC*9; i += 256) ws[i] = w[i];
    if (threadIdx.x < NRC) bs[threadIdx.x] = bv[threadIdx.x];
    __syncthreads();
    int t = blockIdx.x*256 + threadIdx.x;             // 0..32767
    int b = t >> 12, pix = t & 4095, y = pix >> 6, x = pix & 63;
    float acc[NRC];
    #pragma unroll
    for (int r = 0; r < NRC; r++) acc[r] = bs[r];
    const float* in = g_cpre + (size_t)b*NRC*HW;
    #pragma unroll
    for (int ic = 0; ic < NRC; ic++){
        #pragma unroll
        for (int dy = -1; dy <= 1; dy++){
            int yy = y + dy; if (yy < 0 || yy > 63) continue;
            #pragma unroll
            for (int dx = -1; dx <= 1; dx++){
                int xx = x + dx; if (xx < 0 || xx > 63) continue;
                float v = in[ic*HW + yy*64 + xx];
                int tap = ic*9 + (dy+1)*3 + (dx+1);
                #pragma unroll
                for (int oc = 0; oc < NRC; oc++)
                    acc[oc] = fmaf(ws[oc*72 + tap], v, acc[oc]);
            }
        }
    }
    float m = 0.f, a = 0.f;
    float* oc_out = g_car + (size_t)b*NRC*HW + pix;
    #pragma unroll
    for (int r = 0; r < NRC; r++){
        float c = geluf(acc[r]);
        oc_out[r*HW] = c;
        m += c; a += fabsf(c);
    }
    g_cm[t] = m * 0.125f;
    g_dn[t] = a * 0.125f;
}

// ---------------- K3: hp = cm - avg3(cm); cs = avg3(|hp|) ----------------
__global__ __launch_bounds__(256) void k3_hp(){
    __shared__ float cms[20*20];
    __shared__ float hps[18*18];
    int blk = blockIdx.x; int b = blk >> 4; int tile = blk & 15;
    int ty0 = (tile >> 2) << 4, tx0 = (tile & 3) << 4;
    const float* cm = g_cm + b*HW;
    for (int i = threadIdx.x; i < 400; i += 256){
        int ly = i/20, lx = i%20;
        int gy = ty0-2+ly, gx = tx0-2+lx;
        cms[i] = (gy>=0 && gy<64 && gx>=0 && gx<64) ? cm[gy*64+gx] : 0.f;
    }
    __syncthreads();
    for (int i = threadIdx.x; i < 324; i += 256){
        int ly = i/18, lx = i%18;
        int gy = ty0-1+ly, gx = tx0-1+lx;
        float v = 0.f;
        if (gy>=0 && gy<64 && gx>=0 && gx<64){
            float s = 0.f;
            #pragma unroll
            for (int dy = 0; dy < 3; dy++)
                #pragma unroll
                for (int dx = 0; dx < 3; dx++) s += cms[(ly+dy)*20 + (lx+dx)];
            v = cms[(ly+1)*20 + (lx+1)] - s*(1.0f/9.0f);
        }
        hps[i] = v;
    }
    __syncthreads();
    int ty = threadIdx.x >> 4, tx = threadIdx.x & 15;
    int gy = ty0 + ty, gx = tx0 + tx;
    float s = 0.f;
    #pragma unroll
    for (int dy = 0; dy < 3; dy++)
        #pragma unroll
        for (int dx = 0; dx < 3; dx++) s += fabsf(hps[(ty+dy)*18 + (tx+dx)]);
    int gi = b*HW + gy*64 + gx;
    g_hp[gi] = hps[(ty+1)*18 + (tx+1)];
    g_cs[gi] = s*(1.0f/9.0f);
}

// ---------------- K4: per-image reductions ----------------
__global__ __launch_bounds__(256) void k4_stats(){
    int b = blockIdx.x;
    const float* cs = g_cs + b*HW; const float* dn = g_dn + b*HW;
    float cmn = 1e30f, cmx = -1e30f, dmn = 1e30f, dmx = -1e30f, ds = 0.f;
    for (int i = threadIdx.x; i < HW; i += 256){
        float c = cs[i]; cmn = fminf(cmn, c); cmx = fmaxf(cmx, c);
        float d = dn[i]; dmn = fminf(dmn, d); dmx = fmaxf(dmx, d); ds += d;
    }
    __shared__ float r0[256], r1[256], r2[256], r3[256], r4[256];
    r0[threadIdx.x]=cmn; r1[threadIdx.x]=cmx; r2[threadIdx.x]=dmn; r3[threadIdx.x]=dmx; r4[threadIdx.x]=ds;
    __syncthreads();
    for (int s = 128; s > 0; s >>= 1){
        if (threadIdx.x < s){
            r0[threadIdx.x] = fminf(r0[threadIdx.x], r0[threadIdx.x+s]);
            r1[threadIdx.x] = fmaxf(r1[threadIdx.x], r1[threadIdx.x+s]);
            r2[threadIdx.x] = fminf(r2[threadIdx.x], r2[threadIdx.x+s]);
            r3[threadIdx.x] = fmaxf(r3[threadIdx.x], r3[threadIdx.x+s]);
            r4[threadIdx.x] += r4[threadIdx.x+s];
        }
        __syncthreads();
    }
    if (threadIdx.x == 0){
        float* st = g_st + b*8;
        st[0]=r0[0]; st[1]=r1[0]; st[2]=r2[0]; st[3]=r3[0]; st[4]=r4[0]*(1.0f/4096.0f);
    }
}

// ---------------- K5: bank + top2-softmax responses + ev/gate0 + erosion ----------------
__global__ __launch_bounds__(256) void k5_main(const float* __restrict__ theta,
                                               const float* __restrict__ length,
                                               const float* __restrict__ width,
                                               const float* __restrict__ plog,
                                               const float* __restrict__ pdelta){
    __shared__ float hps[24*24];
    __shared__ float ridge[NP*81];
    __shared__ float kern[NP*81];
    __shared__ float m0s[20*20];
    int blk = blockIdx.x; int b = blk >> 4; int tile = blk & 15;
    int ty0 = (tile >> 2) << 4, tx0 = (tile & 3) << 4;

    const float* hp = g_hp + b*HW;
    for (int i = threadIdx.x; i < 576; i += 256){
        int ly = i/24, lx = i%24;
        int gy = ty0-4+ly, gx = tx0-4+lx;
        hps[i] = (gy>=0 && gy<64 && gx>=0 && gx<64) ? hp[gy*64+gx] : 0.f;
    }
    // ridge bank (exactly mirrors reference _build_bank, fp32 math)
    for (int i = threadIdx.x; i < NP*81; i += 256){
        int p = i/81, idx = i%81, ky = idx/9, kx = idx%9;
        float yy = -1.0f + 0.25f*ky, xx = -1.0f + 0.25f*kx;
        double ang = 6.283185307179586 * p / 8.0;
        float ca = (float)cos(ang), sa = (float)sin(ang);
        const float Ls[3] = {0.45f, 0.75f, 1.05f};
        const float Wv[3] = {0.14f, 0.2f, 0.28f};
        float L = Ls[p%3], W = Wv[(p/3)%3];
        float xr = xx*ca + yy*sa;
        float yr = -xx*sa + yy*ca;
        float tp = powf(1.0f - fminf(fabsf(xr)/L, 1.0f), 1.5f);
        float yrw = yr / W;
        float core = expf(-0.5f*((xr/L)*(xr/L) + yrw*yrw));
        ridge[i] = tp * core * fmaxf(1.0f - yrw*yrw, 0.0f);
    }
    __syncthreads();
    if (threadIdx.x < NP){
        int p = threadIdx.x;
        float s = 0.f;
        for (int j = 0; j < 81; j++) s += ridge[p*81+j];
        float mean = s*(1.0f/81.0f);
        float a = 0.f;
        for (int j = 0; j < 81; j++) a += fabsf(ridge[p*81+j]-mean);
        float den = fmaxf(a, 1e-6f);
        for (int j = 0; j < 81; j++)
            kern[p*81+j] = (ridge[p*81+j]-mean)/den + 0.05f*pdelta[p*81+j];
    }
    // stats
    const float* st = g_st + b*8;
    float csmn = st[0], csmx = st[1], dmn = st[2], dmx = st[3];
    float m = fmaxf(st[4], 1e-6f);
    float csden = fmaxf(csmx - csmn, 1e-6f);
    float ddmn = dmn/m, ddmx = dmx/m;
    float dsden = fmaxf(ddmx - ddmn, 1e-6f);
    // binary mask tile (halo 2); 1.0 = neutral for min outside image
    const float* csb = g_cs + b*HW; const float* dnb = g_dn + b*HW;
    for (int i = threadIdx.x; i < 400; i += 256){
        int ly = i/20, lx = i%20;
        int gy = ty0-2+ly, gx = tx0-2+lx;
        float v = 1.0f;
        if (gy>=0 && gy<64 && gx>=0 && gx<64){
            int gi = gy*64+gx;
            float csn = (csb[gi]-csmn)/csden;
            float dsn = (dnb[gi]/m - ddmn)/dsden;
            float ev = 0.65f*csn + 0.35f*dsn;
            v = (ev >= 0.2f) ? 1.0f : 0.0f;
        }
        m0s[i] = v;
    }
    __syncthreads();

    int ty = threadIdx.x >> 4, tx = threadIdx.x & 15;
    int gy = ty0 + ty, gx = tx0 + tx;
    int gi = gy*64 + gx; int t = b*HW + gi;
    // gate0
    {
        float csn = (csb[gi]-csmn)/csden;
        float dsn = (dnb[gi]/m - ddmn)/dsden;
        float ev = 0.65f*csn + 0.35f*dsn;
        g_g0[t] = sigm((ev - 0.2f)/0.08f);
    }
    // eroded = min over in-range 5x5 of binary mask
    {
        float e = 1.0f;
        #pragma unroll
        for (int dy = 0; dy < 5; dy++)
            #pragma unroll
            for (int dx = 0; dx < 5; dx++) e = fminf(e, m0s[(ty+dy)*20 + (tx+dx)]);
        g_er[t] = e;
    }
    // prototype bias + top2 (softmax-sparse) + only 2 of 8 responses
    float bias[NP];
    float ta = tanhf(theta[t]) * 3.14159265358979323846f;
    float lv = sigm(length[t])*0.85f + 0.25f;
    float wv = sigm(width[t])*0.22f + 0.08f;
    const float Ls[3] = {0.45f, 0.75f, 1.05f};
    const float Wv[3] = {0.14f, 0.2f, 0.28f};
    #pragma unroll
    for (int p = 0; p < NP; p++){
        double angd = 6.283185307179586 * p / 8.0;
        float ori = (float)angd;
        float la = Ls[p%3], wa = Wv[(p/3)%3];
        float dl = lv - la, dw = wv - wa;
        bias[p] = plog[(size_t)b*NP*HW + p*HW + gi]
                + 1.25f*cosf(ta - ori)
                - dl*dl/0.08f
                - dw*dw/0.01f;
    }
    int i1 = 0; float m1 = bias[0];
    #pragma unroll
    for (int p = 1; p < NP; p++) if (bias[p] > m1){ m1 = bias[p]; i1 = p; }
    int i2 = (i1 == 0) ? 1 : 0; float m2 = -1e30f;
    #pragma unroll
    for (int p = 0; p < NP; p++) if (p != i1 && bias[p] > m2){ m2 = bias[p]; i2 = p; }
    float e2 = expf(m2 - m1);
    float inv = 1.0f/(1.0f + e2);
    float pw1 = inv, pw2 = e2*inv;

    const float* k1p = kern + i1*81;
    const float* k2p = kern + i2*81;
    float r1 = 0.f, r2v = 0.f;
    #pragma unroll
    for (int ky = 0; ky < 9; ky++){
        #pragma unroll
        for (int kx = 0; kx < 9; kx++){
            float v = hps[(ty+ky)*24 + (tx+kx)];
            r1  = fmaf(k1p[ky*9+kx], v, r1);
            r2v = fmaf(k2p[ky*9+kx], v, r2v);
        }
    }
    g_s0[t] = pw1*r1 + pw2*r2v;
}

// ---------------- K7: dilate/open combine + stroke gate + final ss ----------------
__global__ __launch_bounds__(256) void k7_comb(const float* __restrict__ obj,
                                               const float* __restrict__ alpha,
                                               const float* __restrict__ curv){
    int t = blockIdx.x*256 + threadIdx.x;
    int b = t >> 12, pix = t & 4095, y = pix >> 6, x = pix & 63;
    const float* er = g_er + b*HW;
    const float* g0 = g_g0 + b*HW;
    const float* s0 = g_s0 + b*HW;
    // mask = maxp5(maxp5(eroded)) = maxp9(eroded), in-range
    float mask = 0.f;
    {
        int y0 = max(y-4,0), y1 = min(y+4,63), x0 = max(x-4,0), x1 = min(x+4,63);
        for (int yy = y0; yy <= y1; yy++)
            for (int xx = x0; xx <= x1; xx++) mask = fmaxf(mask, er[yy*64+xx]);
    }
    // gate = maxp5(gate0)
    float gate = 0.f;
    {
        int y0 = max(y-2,0), y1 = min(y+2,63), x0 = max(x-2,0), x1 = min(x+2,63);
        for (int yy = y0; yy <= y1; yy++)
            for (int xx = x0; xx <= x1; xx++) gate = fmaxf(gate, g0[yy*64+xx]);
    }
    // blob = avg3(sigmoid(obj)); ss1 = s0 - avg3(s0)  (zero pad, /9)
    float blob = 0.f, ssum = 0.f;
    const float* ob = obj + b*HW;
    {
        int y0 = max(y-1,0), y1 = min(y+1,63), x0 = max(x-1,0), x1 = min(x+1,63);
        for (int yy = y0; yy <= y1; yy++)
            for (int xx = x0; xx <= x1; xx++){
                blob += sigm(ob[yy*64+xx]);
                ssum += s0[yy*64+xx];
            }
    }
    blob *= (1.0f/9.0f);
    float ss1 = s0[pix] - ssum*(1.0f/9.0f);
    float gatef = gate * mask;
    float dmean = fmaxf(g_st[b*8+4], 1e-6f);
    float dens = g_dn[t] / dmean;
    float sg = sigm(alpha[t]) * (blob * gatef) * (0.7f + 0.3f*fminf(fmaxf(dens, 0.f), 2.f));
    g_sf[t] = sg * ss1 * (1.0f + 0.15f*tanhf(curv[t]));
}

// ---------------- K8: feats -> 8 (gelu) -> 768 expansion (writes 100MB) ----------------
__global__ __launch_bounds__(128) void k8_out(const float* __restrict__ theta,
                                              const float* __restrict__ curv,
                                              const float* __restrict__ w1,
                                              const float* __restrict__ b1,
                                              const float* __restrict__ w2,
                                              const float* __restrict__ b2,
                                              float* __restrict__ out){
    extern __shared__ ull sh[];
    ull*   w2p = sh;                                  // 6144 packed pairs
    float* b2s = (float*)(sh + NFC*NRC);              // 768
    ull*   w1p = (ull*)(b2s + NFC);                   // 96
    float* b1s = (float*)(w1p + 96);                  // 8
    for (int i = threadIdx.x; i < NFC*NRC; i += 128){ float v = w2[i]; w2p[i] = pack2(v, v); }
    for (int i = threadIdx.x; i < NFC; i += 128) b2s[i] = b2[i];
    for (int i = threadIdx.x; i < 96; i += 128){ float v = w1[i]; w1p[i] = pack2(v, v); }
    if (threadIdx.x < 8) b1s[threadIdx.x] = b1[threadIdx.x];
    __syncthreads();

    int t = blockIdx.x*128 + threadIdx.x;
    int b = t >> 11; int p = (t & 2047) << 1;
    int base = b*HW + p;
    float2 ss = *(const float2*)(g_sf + base);
    float2 th = *(const float2*)(theta + base);
    float2 cv = *(const float2*)(curv + base);
    ull f[12];
    const float* car = g_car + (size_t)b*NRC*HW + p;
    #pragma unroll
    for (int r = 0; r < NRC; r++){
        float2 c = *(const float2*)(car + (size_t)r*HW);
        f[r] = pack2(c.x*ss.x, c.y*ss.y);
    }
    f[8] = pack2(ss.x, ss.y);
    const float PIF = 3.14159265358979323846f;
    float a0 = tanhf(th.x)*PIF, a1 = tanhf(th.y)*PIF;
    f[9]  = pack2(cosf(a0)*ss.x, cosf(a1)*ss.y);
    f[10] = pack2(sinf(a0)*ss.x, sinf(a1)*ss.y);
    f[11] = pack2(tanhf(cv.x)*ss.x, tanhf(cv.y)*ss.y);

    ull h[NRC];
    #pragma unroll
    for (int r = 0; r < NRC; r++){
        ull acc = pack2(b1s[r], b1s[r]);
        #pragma unroll
        for (int j = 0; j < 12; j++) acc = fma2(w1p[r*12+j], f[j], acc);
        float lo, hi; unpack2(acc, lo, hi);
        h[r] = pack2(geluf(lo), geluf(hi));
    }
    float* o = out + (size_t)b*NFC*HW + p;
    #pragma unroll 4
    for (int fc = 0; fc < NFC; fc++){
        float bb = b2s[fc];
        ull acc = pack2(bb, bb);
        const ull* wr = w2p + fc*8;
        #pragma unroll
        for (int r = 0; r < NRC; r++) acc = fma2(wr[r], h[r], acc);
        float2 v; unpack2(acc, v.x, v.y);
        *(float2*)(o + (size_t)fc*HW) = v;
    }
}

// ---------------- host ----------------
extern "C" void kernel_launch(void* const* d_in, const int* in_sizes, int n_in,
                              void* d_out, int out_size){
    const float* fm    = (const float*)d_in[0];
    const float* theta = (const float*)d_in[1];
    const float* len   = (const float*)d_in[2];
    const float* wid   = (const float*)d_in[3];
    const float* curv  = (const float*)d_in[4];
    const float* alpha = (const float*)d_in[5];
    const float* obj   = (const float*)d_in[6];
    const float* plog  = (const float*)d_in[7];
    const float* fp1w  = (const float*)d_in[8];
    const float* fp1b  = (const float*)d_in[9];
    const float* fp2w  = (const float*)d_in[10];
    const float* fp2b  = (const float*)d_in[11];
    const float* pm1w  = (const float*)d_in[12];
    const float* pm1b  = (const float*)d_in[13];
    const float* pm2w  = (const float*)d_in[14];
    const float* pm2b  = (const float*)d_in[15];
    const float* pdel  = (const float*)d_in[16];

    cudaFuncSetAttribute(k8_out, cudaFuncAttributeMaxDynamicSharedMemorySize, 53056);

    k1_gemm<<<128,128>>>(fm, fp1w, fp1b);
    k2_conv3<<<128,256>>>(fp2w, fp2b);
    k3_hp<<<128,256>>>();
    k4_stats<<<8,256>>>();
    k5_main<<<128,256>>>(theta, len, wid, plog, pdel);
    k7_comb<<<128,256>>>(obj, alpha, curv);
    k8_out<<<128,128,53056>>>(theta, curv, pm1w, pm1b, pm2w, pm2b, (float*)d_out);
}

// round 5
// speedup vs baseline: 1.1053x; 1.1053x over previous
#include <cuda_runtime.h>
#include <math.h>

#define HW   4096
#define NB   8
#define NFC  768
#define NRC  8
#define NP   8

typedef unsigned long long ull;

// ---------------- scratch ----------------
__device__ float g_cpre[NB*NRC*HW];
__device__ float g_car [NB*NRC*HW];
__device__ float g_cm  [NB*HW];
__device__ float g_dn  [NB*HW];
__device__ float g_hp  [NB*HW];
__device__ float g_cs  [NB*HW];
__device__ float g_g0  [NB*HW];
__device__ float g_er  [NB*HW];
__device__ float g_s0  [NB*HW];
__device__ float g_sf  [NB*HW];
__device__ float g_st  [NB*8];

// ---------------- helpers ----------------
__device__ __forceinline__ ull pack2(float lo, float hi){ ull r; asm("mov.b64 %0,{%1,%2};":"=l"(r):"f"(lo),"f"(hi)); return r; }
__device__ __forceinline__ ull fma2(ull a, ull b, ull c){ ull d; asm("fma.rn.f32x2 %0,%1,%2,%3;":"=l"(d):"l"(a),"l"(b),"l"(c)); return d; }
__device__ __forceinline__ void unpack2(ull v, float&lo, float&hi){ asm("mov.b64 {%0,%1},%2;":"=f"(lo),"=f"(hi):"l"(v)); }
__device__ __forceinline__ float geluf(float x){ return 0.5f*x*(1.0f+erff(x*0.70710678118654752f)); }
__device__ __forceinline__ float sigm(float x){ return 1.0f/(1.0f+expf(-x)); }

// ---------------- K1: 768 -> 8 1x1 conv + gelu; 2-way K-split per pixel pair ----------------
__global__ __launch_bounds__(256) void k1_gemm(const float* __restrict__ fm,
                                               const float* __restrict__ w,
                                               const float* __restrict__ bv){
    __shared__ ull ws[NFC*NRC];                       // (w,w) packed, c-major
    for (int i = threadIdx.x; i < NFC*NRC; i += 256){
        int c = i >> 3, r = i & 7;
        float v = w[r*NFC + c];
        ws[i] = pack2(v, v);
    }
    __syncthreads();
    int t = blockIdx.x*256 + threadIdx.x;             // 0..32767
    int pair = t >> 1, s = t & 1;                     // split half
    int b = pair >> 11; int p = (pair & 2047) << 1;   // pixel pair
    const float* x = fm + (size_t)b*NFC*HW + p + (size_t)(s*384)*HW;
    const ull* wsp = ws + s*384*8;
    ull acc[NRC];
    #pragma unroll
    for (int r = 0; r < NRC; r++){
        float bb = s ? 0.0f : bv[r];
        acc[r] = pack2(bb, bb);
    }
    #pragma unroll 8
    for (int c = 0; c < 384; c++){
        ull xv = *(const ull*)(x + (size_t)c*HW);
        const ull* wc = wsp + c*8;
        #pragma unroll
        for (int r = 0; r < NRC; r++) acc[r] = fma2(wc[r], xv, acc[r]);
    }
    // combine partner halves (lane xor 1), each lane writes 4 of 8 channels
    float* o = g_cpre + (size_t)b*NRC*HW + p;
    #pragma unroll
    for (int r = 0; r < NRC; r++){
        ull other = __shfl_xor_sync(0xffffffffu, acc[r], 1);
        float lo0, hi0, lo1, hi1;
        unpack2(acc[r], lo0, hi0); unpack2(other, lo1, hi1);
        float lo = lo0 + lo1, hi = hi0 + hi1;
        if ((r >> 2) == s){
            float2 v; v.x = geluf(lo); v.y = geluf(hi);
            *(float2*)(o + (size_t)r*HW) = v;
        }
    }
}

// ---------------- K2: 3x3 conv 8->8 + gelu + channel stats ----------------
__global__ __launch_bounds__(256) void k2_conv3(const float* __restrict__ w,
                                                const float* __restrict__ bv){
    __shared__ float ws[NRC*NRC*9];
    __shared__ float bs[NRC];
    for (int i = threadIdx.x; i < NRC*NRC*9; i += 256) ws[i] = w[i];
    if (threadIdx.x < NRC) bs[threadIdx.x] = bv[threadIdx.x];
    __syncthreads();
    int t = blockIdx.x*256 + threadIdx.x;
    int b = t >> 12, pix = t & 4095, y = pix >> 6, x = pix & 63;
    float acc[NRC];
    #pragma unroll
    for (int r = 0; r < NRC; r++) acc[r] = bs[r];
    const float* in = g_cpre + (size_t)b*NRC*HW;
    #pragma unroll
    for (int ic = 0; ic < NRC; ic++){
        #pragma unroll
        for (int dy = -1; dy <= 1; dy++){
            int yy = y + dy; if (yy < 0 || yy > 63) continue;
            #pragma unroll
            for (int dx = -1; dx <= 1; dx++){
                int xx = x + dx; if (xx < 0 || xx > 63) continue;
                float v = in[ic*HW + yy*64 + xx];
                int tap = ic*9 + (dy+1)*3 + (dx+1);
                #pragma unroll
                for (int oc = 0; oc < NRC; oc++)
                    acc[oc] = fmaf(ws[oc*72 + tap], v, acc[oc]);
            }
        }
    }
    float m = 0.f, a = 0.f;
    float* oc_out = g_car + (size_t)b*NRC*HW + pix;
    #pragma unroll
    for (int r = 0; r < NRC; r++){
        float c = geluf(acc[r]);
        oc_out[r*HW] = c;
        m += c; a += fabsf(c);
    }
    g_cm[t] = m * 0.125f;
    g_dn[t] = a * 0.125f;
}

// ---------------- K3+K4 fused: whole image per block; hp, cs, and stats ----------------
__global__ __launch_bounds__(1024) void k3_hp_stats(){
    int b = blockIdx.x;
    __shared__ float cms[64*64];
    __shared__ float hps[66*68];
    __shared__ float red[5][32];
    int tid = threadIdx.x;
    const float* cm = g_cm + b*HW;
    float4 c4 = ((const float4*)cm)[tid];
    ((float4*)cms)[tid] = c4;
    if (tid < 66){
        hps[tid] = 0.f; hps[65*68 + tid] = 0.f;
        hps[tid*68] = 0.f; hps[tid*68 + 65] = 0.f;
    }
    __syncthreads();
    int y = tid >> 4, x0 = (tid & 15) << 2;
    float4 hp4;
    float* hp4p = &hp4.x;
    #pragma unroll
    for (int k = 0; k < 4; k++){
        int x = x0 + k;
        float s = 0.f;
        #pragma unroll
        for (int dy = -1; dy <= 1; dy++){
            int yy = y + dy; if (yy < 0 || yy > 63) continue;
            #pragma unroll
            for (int dx = -1; dx <= 1; dx++){
                int xx = x + dx; if (xx < 0 || xx > 63) continue;
                s += cms[yy*64 + xx];
            }
        }
        float h = cms[y*64 + x] - s*(1.0f/9.0f);
        hp4p[k] = h;
        hps[(y+1)*68 + (x+1)] = h;
    }
    ((float4*)(g_hp + b*HW))[tid] = hp4;
    __syncthreads();
    float cmn = 1e30f, cmx = -1e30f;
    float4 cs4;
    float* cs4p = &cs4.x;
    #pragma unroll
    for (int k = 0; k < 4; k++){
        int x = x0 + k;
        float s = 0.f;
        #pragma unroll
        for (int dy = 0; dy < 3; dy++)
            #pragma unroll
            for (int dx = 0; dx < 3; dx++)
                s += fabsf(hps[(y+dy)*68 + (x+dx)]);
        float cs = s*(1.0f/9.0f);
        cs4p[k] = cs;
        cmn = fminf(cmn, cs); cmx = fmaxf(cmx, cs);
    }
    ((float4*)(g_cs + b*HW))[tid] = cs4;
    float4 d4 = ((const float4*)(g_dn + b*HW))[tid];
    float dmn = fminf(fminf(d4.x, d4.y), fminf(d4.z, d4.w));
    float dmx = fmaxf(fmaxf(d4.x, d4.y), fmaxf(d4.z, d4.w));
    float ds  = (d4.x + d4.y) + (d4.z + d4.w);
    // warp reduce
    #pragma unroll
    for (int o = 16; o > 0; o >>= 1){
        cmn = fminf(cmn, __shfl_xor_sync(0xffffffffu, cmn, o));
        cmx = fmaxf(cmx, __shfl_xor_sync(0xffffffffu, cmx, o));
        dmn = fminf(dmn, __shfl_xor_sync(0xffffffffu, dmn, o));
        dmx = fmaxf(dmx, __shfl_xor_sync(0xffffffffu, dmx, o));
        ds += __shfl_xor_sync(0xffffffffu, ds, o);
    }
    int wid = tid >> 5, lane = tid & 31;
    if (lane == 0){ red[0][wid]=cmn; red[1][wid]=cmx; red[2][wid]=dmn; red[3][wid]=dmx; red[4][wid]=ds; }
    __syncthreads();
    if (tid < 32){
        cmn = red[0][tid]; cmx = red[1][tid]; dmn = red[2][tid]; dmx = red[3][tid]; ds = red[4][tid];
        #pragma unroll
        for (int o = 16; o > 0; o >>= 1){
            cmn = fminf(cmn, __shfl_xor_sync(0xffffffffu, cmn, o));
            cmx = fmaxf(cmx, __shfl_xor_sync(0xffffffffu, cmx, o));
            dmn = fminf(dmn, __shfl_xor_sync(0xffffffffu, dmn, o));
            dmx = fmaxf(dmx, __shfl_xor_sync(0xffffffffu, dmx, o));
            ds += __shfl_xor_sync(0xffffffffu, ds, o);
        }
        if (tid == 0){
            float* st = g_st + b*8;
            st[0]=cmn; st[1]=cmx; st[2]=dmn; st[3]=dmx; st[4]=ds*(1.0f/4096.0f);
        }
    }
}

// ---------------- K5: bank + top2-softmax responses + ev/gate0 + erosion ----------------
__global__ __launch_bounds__(256) void k5_main(const float* __restrict__ theta,
                                               const float* __restrict__ length,
                                               const float* __restrict__ width,
                                               const float* __restrict__ plog,
                                               const float* __restrict__ pdelta){
    __shared__ float hps[24*24];
    __shared__ float ridge[NP*81];
    __shared__ float kern[NP*81];
    __shared__ float m0s[20*20];
    int blk = blockIdx.x; int b = blk >> 4; int tile = blk & 15;
    int ty0 = (tile >> 2) << 4, tx0 = (tile & 3) << 4;

    const float* hp = g_hp + b*HW;
    for (int i = threadIdx.x; i < 576; i += 256){
        int ly = i/24, lx = i%24;
        int gy = ty0-4+ly, gx = tx0-4+lx;
        hps[i] = (gy>=0 && gy<64 && gx>=0 && gx<64) ? hp[gy*64+gx] : 0.f;
    }
    for (int i = threadIdx.x; i < NP*81; i += 256){
        int p = i/81, idx = i%81, ky = idx/9, kx = idx%9;
        float yy = -1.0f + 0.25f*ky, xx = -1.0f + 0.25f*kx;
        double ang = 6.283185307179586 * p / 8.0;
        float ca = (float)cos(ang), sa = (float)sin(ang);
        const float Ls[3] = {0.45f, 0.75f, 1.05f};
        const float Wv[3] = {0.14f, 0.2f, 0.28f};
        float L = Ls[p%3], W = Wv[(p/3)%3];
        float xr = xx*ca + yy*sa;
        float yr = -xx*sa + yy*ca;
        float tp = powf(1.0f - fminf(fabsf(xr)/L, 1.0f), 1.5f);
        float yrw = yr / W;
        float core = expf(-0.5f*((xr/L)*(xr/L) + yrw*yrw));
        ridge[i] = tp * core * fmaxf(1.0f - yrw*yrw, 0.0f);
    }
    __syncthreads();
    if (threadIdx.x < NP){
        int p = threadIdx.x;
        float s = 0.f;
        for (int j = 0; j < 81; j++) s += ridge[p*81+j];
        float mean = s*(1.0f/81.0f);
        float a = 0.f;
        for (int j = 0; j < 81; j++) a += fabsf(ridge[p*81+j]-mean);
        float den = fmaxf(a, 1e-6f);
        for (int j = 0; j < 81; j++)
            kern[p*81+j] = (ridge[p*81+j]-mean)/den + 0.05f*pdelta[p*81+j];
    }
    const float* st = g_st + b*8;
    float csmn = st[0], csmx = st[1], dmn = st[2], dmx = st[3];
    float m = fmaxf(st[4], 1e-6f);
    float csden = fmaxf(csmx - csmn, 1e-6f);
    float ddmn = dmn/m, ddmx = dmx/m;
    float dsden = fmaxf(ddmx - ddmn, 1e-6f);
    const float* csb = g_cs + b*HW; const float* dnb = g_dn + b*HW;
    for (int i = threadIdx.x; i < 400; i += 256){
        int ly = i/20, lx = i%20;
        int gy = ty0-2+ly, gx = tx0-2+lx;
        float v = 1.0f;
        if (gy>=0 && gy<64 && gx>=0 && gx<64){
            int gi = gy*64+gx;
            float csn = (csb[gi]-csmn)/csden;
            float dsn = (dnb[gi]/m - ddmn)/dsden;
            float ev = 0.65f*csn + 0.35f*dsn;
            v = (ev >= 0.2f) ? 1.0f : 0.0f;
        }
        m0s[i] = v;
    }
    __syncthreads();

    int ty = threadIdx.x >> 4, tx = threadIdx.x & 15;
    int gy = ty0 + ty, gx = tx0 + tx;
    int gi = gy*64 + gx; int t = b*HW + gi;
    {
        float csn = (csb[gi]-csmn)/csden;
        float dsn = (dnb[gi]/m - ddmn)/dsden;
        float ev = 0.65f*csn + 0.35f*dsn;
        g_g0[t] = sigm((ev - 0.2f)/0.08f);
    }
    {
        float e = 1.0f;
        #pragma unroll
        for (int dy = 0; dy < 5; dy++)
            #pragma unroll
            for (int dx = 0; dx < 5; dx++) e = fminf(e, m0s[(ty+dy)*20 + (tx+dx)]);
        g_er[t] = e;
    }
    float bias[NP];
    float ta = tanhf(theta[t]) * 3.14159265358979323846f;
    float lv = sigm(length[t])*0.85f + 0.25f;
    float wv = sigm(width[t])*0.22f + 0.08f;
    const float Ls[3] = {0.45f, 0.75f, 1.05f};
    const float Wv[3] = {0.14f, 0.2f, 0.28f};
    #pragma unroll
    for (int p = 0; p < NP; p++){
        double angd = 6.283185307179586 * p / 8.0;
        float ori = (float)angd;
        float la = Ls[p%3], wa = Wv[(p/3)%3];
        float dl = lv - la, dw = wv - wa;
        bias[p] = plog[(size_t)b*NP*HW + p*HW + gi]
                + 1.25f*cosf(ta - ori)
                - dl*dl/0.08f
                - dw*dw/0.01f;
    }
    int i1 = 0; float m1 = bias[0];
    #pragma unroll
    for (int p = 1; p < NP; p++) if (bias[p] > m1){ m1 = bias[p]; i1 = p; }
    int i2 = (i1 == 0) ? 1 : 0; float m2 = -1e30f;
    #pragma unroll
    for (int p = 0; p < NP; p++) if (p != i1 && bias[p] > m2){ m2 = bias[p]; i2 = p; }
    float e2 = expf(m2 - m1);
    float inv = 1.0f/(1.0f + e2);
    float pw1 = inv, pw2 = e2*inv;

    const float* k1p = kern + i1*81;
    const float* k2p = kern + i2*81;
    float r1 = 0.f, r2v = 0.f;
    #pragma unroll
    for (int ky = 0; ky < 9; ky++){
        #pragma unroll
        for (int kx = 0; kx < 9; kx++){
            float v = hps[(ty+ky)*24 + (tx+kx)];
            r1  = fmaf(k1p[ky*9+kx], v, r1);
            r2v = fmaf(k2p[ky*9+kx], v, r2v);
        }
    }
    g_s0[t] = pw1*r1 + pw2*r2v;
}

// ---------------- K7: dilate/open combine + stroke gate + final ss ----------------
__global__ __launch_bounds__(256) void k7_comb(const float* __restrict__ obj,
                                               const float* __restrict__ alpha,
                                               const float* __restrict__ curv){
    int t = blockIdx.x*256 + threadIdx.x;
    int b = t >> 12, pix = t & 4095, y = pix >> 6, x = pix & 63;
    const float* er = g_er + b*HW;
    const float* g0 = g_g0 + b*HW;
    const float* s0 = g_s0 + b*HW;
    float mask = 0.f;
    {
        int y0 = max(y-4,0), y1 = min(y+4,63), x0 = max(x-4,0), x1 = min(x+4,63);
        for (int yy = y0; yy <= y1; yy++)
            for (int xx = x0; xx <= x1; xx++) mask = fmaxf(mask, er[yy*64+xx]);
    }
    float gate = 0.f;
    {
        int y0 = max(y-2,0), y1 = min(y+2,63), x0 = max(x-2,0), x1 = min(x+2,63);
        for (int yy = y0; yy <= y1; yy++)
            for (int xx = x0; xx <= x1; xx++) gate = fmaxf(gate, g0[yy*64+xx]);
    }
    float blob = 0.f, ssum = 0.f;
    const float* ob = obj + b*HW;
    {
        int y0 = max(y-1,0), y1 = min(y+1,63), x0 = max(x-1,0), x1 = min(x+1,63);
        for (int yy = y0; yy <= y1; yy++)
            for (int xx = x0; xx <= x1; xx++){
                blob += sigm(ob[yy*64+xx]);
                ssum += s0[yy*64+xx];
            }
    }
    blob *= (1.0f/9.0f);
    float ss1 = s0[pix] - ssum*(1.0f/9.0f);
    float gatef = gate * mask;
    float dmean = fmaxf(g_st[b*8+4], 1e-6f);
    float dens = g_dn[t] / dmean;
    float sg = sigm(alpha[t]) * (blob * gatef) * (0.7f + 0.3f*fminf(fmaxf(dens, 0.f), 2.f));
    g_sf[t] = sg * ss1 * (1.0f + 0.15f*tanhf(curv[t]));
}

// ---------------- K8: feats -> 8 (gelu) -> 768 expansion; 2-way output split ----------------
__global__ __launch_bounds__(256) void k8_out(const float* __restrict__ theta,
                                              const float* __restrict__ curv,
                                              const float* __restrict__ w1,
                                              const float* __restrict__ b1,
                                              const float* __restrict__ w2,
                                              const float* __restrict__ b2,
                                              float* __restrict__ out){
    extern __shared__ ull sh[];
    ull*   w2p = sh;                                  // 6144 packed pairs
    float* b2s = (float*)(sh + NFC*NRC);              // 768
    ull*   w1p = (ull*)(b2s + NFC);                   // 96
    float* b1s = (float*)(w1p + 96);                  // 8
    for (int i = threadIdx.x; i < NFC*NRC; i += 256){ float v = w2[i]; w2p[i] = pack2(v, v); }
    for (int i = threadIdx.x; i < NFC; i += 256) b2s[i] = b2[i];
    for (int i = threadIdx.x; i < 96; i += 256){ float v = w1[i]; w1p[i] = pack2(v, v); }
    if (threadIdx.x < 8) b1s[threadIdx.x] = b1[threadIdx.x];
    __syncthreads();

    int t = blockIdx.x*256 + threadIdx.x;
    int pair = t >> 1, half = t & 1;
    int b = pair >> 11; int p = (pair & 2047) << 1;
    int base = b*HW + p;
    float2 ss = *(const float2*)(g_sf + base);
    float2 th = *(const float2*)(theta + base);
    float2 cv = *(const float2*)(curv + base);
    ull f[12];
    const float* car = g_car + (size_t)b*NRC*HW + p;
    #pragma unroll
    for (int r = 0; r < NRC; r++){
        float2 c = *(const float2*)(car + (size_t)r*HW);
        f[r] = pack2(c.x*ss.x, c.y*ss.y);
    }
    f[8] = pack2(ss.x, ss.y);
    const float PIF = 3.14159265358979323846f;
    float a0 = tanhf(th.x)*PIF, a1 = tanhf(th.y)*PIF;
    f[9]  = pack2(cosf(a0)*ss.x, cosf(a1)*ss.y);
    f[10] = pack2(sinf(a0)*ss.x, sinf(a1)*ss.y);
    f[11] = pack2(tanhf(cv.x)*ss.x, tanhf(cv.y)*ss.y);

    ull h[NRC];
    #pragma unroll
    for (int r = 0; r < NRC; r++){
        ull acc = pack2(b1s[r], b1s[r]);
        #pragma unroll
        for (int j = 0; j < 12; j++) acc = fma2(w1p[r*12+j], f[j], acc);
        float lo, hi; unpack2(acc, lo, hi);
        h[r] = pack2(geluf(lo), geluf(hi));
    }
    float* o = out + (size_t)b*NFC*HW + p;
    int fc0 = half * 384;
    #pragma unroll 4
    for (int j = 0; j < 384; j++){
        int fc = fc0 + j;
        float bb = b2s[fc];
        ull acc = pack2(bb, bb);
        const ull* wr = w2p + fc*8;
        #pragma unroll
        for (int r = 0; r < NRC; r++) acc = fma2(wr[r], h[r], acc);
        float2 v; unpack2(acc, v.x, v.y);
        *(float2*)(o + (size_t)fc*HW) = v;
    }
}

// ---------------- host ----------------
extern "C" void kernel_launch(void* const* d_in, const int* in_sizes, int n_in,
                              void* d_out, int out_size){
    const float* fm    = (const float*)d_in[0];
    const float* theta = (const float*)d_in[1];
    const float* len   = (const float*)d_in[2];
    const float* wid   = (const float*)d_in[3];
    const float* curv  = (const float*)d_in[4];
    const float* alpha = (const float*)d_in[5];
    const float* obj   = (const float*)d_in[6];
    const float* plog  = (const float*)d_in[7];
    const float* fp1w  = (const float*)d_in[8];
    const float* fp1b  = (const float*)d_in[9];
    const float* fp2w  = (const float*)d_in[10];
    const float* fp2b  = (const float*)d_in[11];
    const float* pm1w  = (const float*)d_in[12];
    const float* pm1b  = (const float*)d_in[13];
    const float* pm2w  = (const float*)d_in[14];
    const float* pm2b  = (const float*)d_in[15];
    const float* pdel  = (const float*)d_in[16];

    cudaFuncSetAttribute(k8_out, cudaFuncAttributeMaxDynamicSharedMemorySize, 53056);

    k1_gemm<<<128,256>>>(fm, fp1w, fp1b);
    k2_conv3<<<128,256>>>(fp2w, fp2b);
    k3_hp_stats<<<8,1024>>>();
    k5_main<<<128,256>>>(theta, len, wid, plog, pdel);
    k7_comb<<<128,256>>>(obj, alpha, curv);
    k8_out<<<128,256,53056>>>(theta, curv, pm1w, pm1b, pm2w, pm2b, (float*)d_out);
}